// round 8
// baseline (speedup 1.0000x reference)
#include <cuda_runtime.h>
#include <cuda_bf16.h>

// ---------------------------------------------------------------------------
// Nodes_Embedding: out[a, :] = ELU(ELU(ELU(x W1^T + b1) W2^T + b2) W3^T + b3)
//                              + (float)part[a] + charge[part[a]]
// N = 4M atoms, D = 16.
//
// Harness dtype contract: float32 / int32 / bf16 only -> atom_part (int64 in
// the reference) arrives as int32. Read it as const int*.
//
// Inputs bound BY ELEMENT COUNT (robust to metadata ordering):
//   16*N -> atom_type_vector,  N -> atom_part (int32),  1024 -> atom_charge,
//   256 x3 -> W1,W2,W3 (appearance order), 16 x3 -> b1,b2,b3.
//
// Strategy: fp32x2 packed FMA (FFMA2) over atom-pairs, 4 atoms per thread,
// weights duplicated {w,w} in shared memory (broadcast LDS.64), fully
// unrolled 16x16 inner product, layer loop rolled to keep I$ footprint small.
//
// (R7: resubmit of R6 — previous bench died with cudaErrorSystemNotReady in
// harness setup, an infra fault on the brokered node, before kernel ran.)
// ---------------------------------------------------------------------------

#define FFMA2(acc, xx, ww) \
    asm("fma.rn.f32x2 %0, %1, %2, %0;" : "+l"(acc) : "l"(xx), "l"(ww))

#define ADD2(dst, aa, bb) \
    asm("add.rn.f32x2 %0, %1, %2;" : "=l"(dst) : "l"(aa), "l"(bb))

__device__ __forceinline__ unsigned long long pk2(float lo, float hi) {
    unsigned long long r;
    asm("mov.b64 %0, {%1, %2};" : "=l"(r) : "f"(lo), "f"(hi));
    return r;
}

__device__ __forceinline__ void upk2(unsigned long long v, float& lo, float& hi) {
    asm("mov.b64 {%0, %1}, %2;" : "=f"(lo), "=f"(hi) : "l"(v));
}

// elu(x) = x>0 ? x : exp(x)-1  ==  max(x,0) + min(exp(x)-1, 0)
__device__ __forceinline__ float elu1(float v) {
    float e = __expf(v) - 1.0f;
    return fmaxf(v, 0.0f) + fminf(e, 0.0f);
}

static constexpr int BLOCK = 128;   // threads per block
static constexpr int APT   = 4;     // atoms per thread (2 f32x2 pairs)
static constexpr int ABLK  = BLOCK * APT;  // 512 atoms per block

__global__ void __launch_bounds__(BLOCK)
nodes_embedding_kernel(const float* __restrict__ atv,      // [N,16]
                       const float* __restrict__ charge,   // [nParts]
                       const float* __restrict__ W1, const float* __restrict__ b1,
                       const float* __restrict__ W2, const float* __restrict__ b2,
                       const float* __restrict__ W3, const float* __restrict__ b3,
                       const int* __restrict__ part,       // [N] int32
                       float* __restrict__ out,            // [N,16]
                       int nAtoms, int nParts) {
    // ---- shared: weights duplicated into f32x2 pairs -----------------------
    __shared__ unsigned long long s_w[3][16][16];
    __shared__ unsigned long long s_b[3][16];

    {
        const float* Ws[3] = {W1, W2, W3};
        const float* bs[3] = {b1, b2, b3};
        for (int e = threadIdx.x; e < 3 * 256; e += BLOCK) {
            int l = e >> 8, idx = e & 255;
            float w = Ws[l][idx];
            s_w[l][idx >> 4][idx & 15] = pk2(w, w);
        }
        for (int e = threadIdx.x; e < 3 * 16; e += BLOCK) {
            int l = e >> 4;
            float b = bs[l][e & 15];
            s_b[l][e & 15] = pk2(b, b);
        }
    }
    __syncthreads();

    const int a0 = blockIdx.x * ABLK + threadIdx.x;  // interleaved: atom i = a0 + i*BLOCK

    // ---- load 4 atoms x 16 features (vectorized float4) --------------------
    float xf[APT][16];
#pragma unroll
    for (int i = 0; i < APT; ++i) {
        int ai = a0 + i * BLOCK;
        if (ai < nAtoms) {
            const float4* p = reinterpret_cast<const float4*>(atv + (size_t)ai * 16);
#pragma unroll
            for (int c = 0; c < 4; ++c)
                *reinterpret_cast<float4*>(&xf[i][c * 4]) = p[c];
        } else {
#pragma unroll
            for (int k = 0; k < 16; ++k) xf[i][k] = 0.0f;
        }
    }

    // pack atom-pairs: pair p holds atoms (2p, 2p+1) in (lo, hi)
    unsigned long long x[2][16];
#pragma unroll
    for (int p = 0; p < 2; ++p)
#pragma unroll
        for (int k = 0; k < 16; ++k)
            x[p][k] = pk2(xf[2 * p][k], xf[2 * p + 1][k]);

    // ---- 3 MLP layers (layer loop rolled; 16x16 fully unrolled) ------------
#pragma unroll 1
    for (int l = 0; l < 3; ++l) {
        unsigned long long acc[2][16];
#pragma unroll
        for (int j = 0; j < 16; ++j) {
            unsigned long long A0 = s_b[l][j];
            unsigned long long A1 = A0;
#pragma unroll
            for (int k = 0; k < 16; ++k) {
                unsigned long long w = s_w[l][j][k];
                FFMA2(A0, x[0][k], w);
                FFMA2(A1, x[1][k], w);
            }
            acc[0][j] = A0;
            acc[1][j] = A1;
        }
#pragma unroll
        for (int p = 0; p < 2; ++p)
#pragma unroll
            for (int j = 0; j < 16; ++j) {
                float lo, hi;
                upk2(acc[p][j], lo, hi);
                x[p][j] = pk2(elu1(lo), elu1(hi));
            }
    }

    // ---- add (float)part + charge[part] ------------------------------------
    unsigned long long av[2];
#pragma unroll
    for (int p = 0; p < 2; ++p) {
        float v[2];
#pragma unroll
        for (int h = 0; h < 2; ++h) {
            int ai = a0 + (2 * p + h) * BLOCK;
            v[h] = 0.0f;
            if (ai < nAtoms) {
                int pi = part[ai];
                int pc = pi < 0 ? 0 : (pi >= nParts ? nParts - 1 : pi);  // no OOB ever
                v[h] = (float)pi + charge[pc];
            }
        }
        av[p] = pk2(v[0], v[1]);
    }
#pragma unroll
    for (int p = 0; p < 2; ++p)
#pragma unroll
        for (int j = 0; j < 16; ++j)
            ADD2(x[p][j], x[p][j], av[p]);

    // ---- store -------------------------------------------------------------
#pragma unroll
    for (int i = 0; i < APT; ++i) {
        int ai = a0 + i * BLOCK;
        if (ai >= nAtoms) continue;
        int p = i >> 1;
        bool hiHalf = (i & 1) != 0;
        float o[16];
#pragma unroll
        for (int j = 0; j < 16; ++j) {
            float lo, hi;
            upk2(x[p][j], lo, hi);
            o[j] = hiHalf ? hi : lo;
        }
        float4* po = reinterpret_cast<float4*>(out + (size_t)ai * 16);
#pragma unroll
        for (int c = 0; c < 4; ++c)
            po[c] = *reinterpret_cast<const float4*>(&o[c * 4]);
    }
}

extern "C" void kernel_launch(void* const* d_in, const int* in_sizes, int n_in,
                              void* d_out, int out_size) {
    // ---- bind inputs by element count (order-independent) ------------------
    const float* Ws[3] = {nullptr, nullptr, nullptr};
    const float* bs[3] = {nullptr, nullptr, nullptr};
    const float* charge = nullptr;
    int wi = 0, bi = 0, chargeN = 1024;

    // find the two "large" arrays: features (16*N) and part index (N)
    int bigIdx[2] = {-1, -1};
    long long bigSz[2] = {-1, -1};

    for (int i = 0; i < n_in; ++i) {
        long long s = in_sizes[i];
        if (s == 256 && wi < 3) {
            Ws[wi++] = (const float*)d_in[i];
        } else if (s == 16 && bi < 3) {
            bs[bi++] = (const float*)d_in[i];
        } else if (s >= 512 && s <= 65536 && s != 256) {
            // mid-size array = atom_charge table (1024 nominally)
            charge = (const float*)d_in[i];
            chargeN = (int)s;
        } else if (s > 65536) {
            if (s > bigSz[0]) {
                bigSz[1] = bigSz[0]; bigIdx[1] = bigIdx[0];
                bigSz[0] = s;        bigIdx[0] = i;
            } else if (s > bigSz[1]) {
                bigSz[1] = s;        bigIdx[1] = i;
            }
        }
    }

    const float* atv  = (const float*)d_in[bigIdx[0]];  // 16*N elems
    const int*   part = (const int*)d_in[bigIdx[1]];    // N elems, int32
    float*       out  = (float*)d_out;

    int nAtoms = (int)bigSz[1];          // = N (part element count)
    if ((long long)nAtoms * 16 != bigSz[0]) {
        // fallback: derive from the feature array if ratio is off
        nAtoms = (int)(bigSz[0] / 16);
    }

    int grid = (nAtoms + ABLK - 1) / ABLK;
    nodes_embedding_kernel<<<grid, BLOCK>>>(atv, charge, Ws[0], bs[0], Ws[1], bs[1],
                                            Ws[2], bs[2], part, out, nAtoms, chargeN);
}